// round 16
// baseline (speedup 1.0000x reference)
#include <cuda_runtime.h>
#include <cuda_bf16.h>
#include <mma.h>
#include <cstdint>

using namespace nvcuda;

#define B_  64
#define T_  2048
#define I_  128
#define H_  256
#define C_  64
#define G3  (3 * H_)   // 768

__device__ float g_gates[(size_t)B_ * T_ * G3];
__device__ float g_h[(size_t)B_ * T_ * H_];
__device__ __nv_bfloat16 g_xh[(size_t)B_ * T_ * I_];
__device__ __nv_bfloat16 g_xl[(size_t)B_ * T_ * I_];
__device__ __nv_bfloat16 g_hh[(size_t)B_ * T_ * H_];
__device__ __nv_bfloat16 g_hl[(size_t)B_ * T_ * H_];
__device__ __nv_bfloat16 g_wh[G3 * H_];
__device__ __nv_bfloat16 g_wl[G3 * H_];

// ---------------------------------------------------------------------------
// helpers
// ---------------------------------------------------------------------------
__device__ __forceinline__ float tanh_hw_(float x) {
    float r;
    asm("tanh.approx.f32 %0, %1;" : "=f"(r) : "f"(x));
    return r;
}
__device__ __forceinline__ float sigmoid_hw_(float x) {
    return fmaf(0.5f, tanh_hw_(0.5f * x), 0.5f);
}
__device__ __forceinline__ void fma2_(uint64_t& d, uint64_t a, uint64_t b) {
    asm("fma.rn.f32x2 %0, %1, %2, %0;" : "+l"(d) : "l"(a), "l"(b));
}
__device__ __forceinline__ float f2lo_(uint64_t v) {
    float lo, hi;
    asm("mov.b64 {%0,%1}, %2;" : "=f"(lo), "=f"(hi) : "l"(v));
    return lo;
}
__device__ __forceinline__ float f2hi_(uint64_t v) {
    float lo, hi;
    asm("mov.b64 {%0,%1}, %2;" : "=f"(lo), "=f"(hi) : "l"(v));
    return hi;
}
__device__ __forceinline__ uint64_t dup2_(float x) {
    uint64_t r;
    asm("mov.b64 %0, {%1,%1};" : "=l"(r) : "f"(x));
    return r;
}
__device__ __forceinline__ void mbar_init_(uint32_t a, uint32_t cnt) {
    asm volatile("mbarrier.init.shared.b64 [%0], %1;" :: "r"(a), "r"(cnt) : "memory");
}
__device__ __forceinline__ void mbar_arm_(uint32_t a, uint32_t tx) {
    asm volatile("mbarrier.arrive.expect_tx.shared.b64 _, [%0], %1;"
                 :: "r"(a), "r"(tx) : "memory");
}
__device__ __forceinline__ void mbar_wait_(uint32_t a, uint32_t par) {
    uint32_t done;
    asm volatile(
        "{\n\t.reg .pred p;\n\t"
        "mbarrier.try_wait.parity.acquire.cta.shared::cta.b64 p, [%1], %2;\n\t"
        "selp.b32 %0, 1, 0, p;\n\t}"
        : "=r"(done) : "r"(a), "r"(par) : "memory");
    if (!done) {
        asm volatile(
            "{\n\t.reg .pred P1;\n\t"
            "W_%=:\n\t"
            "mbarrier.try_wait.parity.acquire.cta.shared::cta.b64 P1, [%0], %1, 0x989680;\n\t"
            "@P1 bra.uni D_%=;\n\t"
            "bra.uni W_%=;\n\t"
            "D_%=:\n\t}"
            :: "r"(a), "r"(par) : "memory");
    }
}

// ---------------------------------------------------------------------------
// fp32 -> bf16 hi/lo split (one-shot pre-pass)
// ---------------------------------------------------------------------------
__global__ void cvt_split(const float* __restrict__ in,
                          __nv_bfloat16* __restrict__ hi,
                          __nv_bfloat16* __restrict__ lo, int n4)
{
    int i = blockIdx.x * blockDim.x + threadIdx.x;
    if (i >= n4) return;
    float4 v = ((const float4*)in)[i];
    __nv_bfloat16 h0 = __float2bfloat16(v.x), h1 = __float2bfloat16(v.y);
    __nv_bfloat16 h2 = __float2bfloat16(v.z), h3 = __float2bfloat16(v.w);
    __nv_bfloat162* hp = (__nv_bfloat162*)hi;
    __nv_bfloat162* lp = (__nv_bfloat162*)lo;
    hp[i * 2]     = __nv_bfloat162(h0, h1);
    hp[i * 2 + 1] = __nv_bfloat162(h2, h3);
    lp[i * 2]     = __nv_bfloat162(__float2bfloat16(v.x - __bfloat162float(h0)),
                                   __float2bfloat16(v.y - __bfloat162float(h1)));
    lp[i * 2 + 1] = __nv_bfloat162(__float2bfloat16(v.z - __bfloat162float(h2)),
                                   __float2bfloat16(v.w - __bfloat162float(h3)));
}

// ---------------------------------------------------------------------------
// wmma bf16-split GEMM v2: inputs already split to bf16 hi/lo in GMEM.
// C[m,n] = sum_k A[m,k]*W[n,k] + bias[n];  D = Ah*Wh + Ah*Wl + Al*Wh (fp32).
// CTA 128x64 tile, 256 threads (8 warps = 4x2 grid of 32x32 patches).
// K staged 32/step; zero conversions in the loop.
// ---------------------------------------------------------------------------
#define AST 40                         // smem tile stride (bf16 elems)
#define GW2_SMEM (128 * 72 * 4)        // 36864B; tiles need 30720B (reused)

__global__ void __launch_bounds__(256) gemm_wmma2(
    const __nv_bfloat16* __restrict__ Ahg, const __nv_bfloat16* __restrict__ Alg,
    const __nv_bfloat16* __restrict__ Whg, const __nv_bfloat16* __restrict__ Wlg,
    const float* __restrict__ bias, float* __restrict__ C,
    int N_total, int K)
{
    extern __shared__ char sm[];
    __nv_bfloat16* Ah = (__nv_bfloat16*)sm;            // 128*40
    __nv_bfloat16* Al = Ah + 128 * AST;
    __nv_bfloat16* Bh = Al + 128 * AST;                // 64*40
    __nv_bfloat16* Bl = Bh + 64 * AST;
    float* Cst = (float*)sm;                           // reused post-loop

    const int tid = threadIdx.x;
    const int wid = tid >> 5;
    const int m0 = blockIdx.y * 128;
    const int n0 = blockIdx.x * 64;
    const int mh = (wid & 3) * 32;
    const int nh = (wid >> 2) * 32;

    wmma::fragment<wmma::accumulator, 16, 16, 16, float> acc[2][2];
#pragma unroll
    for (int i = 0; i < 2; i++)
#pragma unroll
        for (int j = 0; j < 2; j++) wmma::fill_fragment(acc[i][j], 0.0f);

    const int arow = tid >> 1, aseg = (tid & 1) * 16;
    const int brow = (tid & 127) >> 1, bseg = (tid & 1) * 16;
    const bool bldr = tid < 128;

    for (int kt = 0; kt < K; kt += 32) {
        // stage A 128x32 hi/lo (32B per thread per array)
        {
            const __nv_bfloat16* ap = &Ahg[(size_t)(m0 + arow) * K + kt + aseg];
            const __nv_bfloat16* lp = &Alg[(size_t)(m0 + arow) * K + kt + aseg];
            *(uint4*)&Ah[arow * AST + aseg]     = *(const uint4*)ap;
            *(uint4*)&Ah[arow * AST + aseg + 8] = *(const uint4*)(ap + 8);
            *(uint4*)&Al[arow * AST + aseg]     = *(const uint4*)lp;
            *(uint4*)&Al[arow * AST + aseg + 8] = *(const uint4*)(lp + 8);
            if (bldr) {
                const __nv_bfloat16* bp = &Whg[(size_t)(n0 + brow) * K + kt + bseg];
                const __nv_bfloat16* ql = &Wlg[(size_t)(n0 + brow) * K + kt + bseg];
                *(uint4*)&Bh[brow * AST + bseg]     = *(const uint4*)bp;
                *(uint4*)&Bh[brow * AST + bseg + 8] = *(const uint4*)(bp + 8);
                *(uint4*)&Bl[brow * AST + bseg]     = *(const uint4*)ql;
                *(uint4*)&Bl[brow * AST + bseg + 8] = *(const uint4*)(ql + 8);
            }
        }
        __syncthreads();

#pragma unroll
        for (int kf = 0; kf < 2; kf++) {
            wmma::fragment<wmma::matrix_a, 16, 16, 16, __nv_bfloat16, wmma::row_major> afh[2], afl[2];
            wmma::fragment<wmma::matrix_b, 16, 16, 16, __nv_bfloat16, wmma::col_major> bfh[2], bfl[2];
#pragma unroll
            for (int i = 0; i < 2; i++)
                wmma::load_matrix_sync(afh[i], &Ah[(mh + i * 16) * AST + kf * 16], AST);
#pragma unroll
            for (int j = 0; j < 2; j++)
                wmma::load_matrix_sync(bfh[j], &Bh[(nh + j * 16) * AST + kf * 16], AST);
#pragma unroll
            for (int i = 0; i < 2; i++)
#pragma unroll
                for (int j = 0; j < 2; j++)
                    wmma::mma_sync(acc[i][j], afh[i], bfh[j], acc[i][j]);

#pragma unroll
            for (int j = 0; j < 2; j++)
                wmma::load_matrix_sync(bfl[j], &Bl[(nh + j * 16) * AST + kf * 16], AST);
#pragma unroll
            for (int i = 0; i < 2; i++)
#pragma unroll
                for (int j = 0; j < 2; j++)
                    wmma::mma_sync(acc[i][j], afh[i], bfl[j], acc[i][j]);

#pragma unroll
            for (int i = 0; i < 2; i++)
                wmma::load_matrix_sync(afl[i], &Al[(mh + i * 16) * AST + kf * 16], AST);
#pragma unroll
            for (int i = 0; i < 2; i++)
#pragma unroll
                for (int j = 0; j < 2; j++)
                    wmma::mma_sync(acc[i][j], afl[i], bfh[j], acc[i][j]);
        }
        __syncthreads();
    }

    // stage accumulators, add bias, write out
#pragma unroll
    for (int i = 0; i < 2; i++)
#pragma unroll
        for (int j = 0; j < 2; j++)
            wmma::store_matrix_sync(&Cst[(mh + i * 16) * 72 + nh + j * 16],
                                    acc[i][j], 72, wmma::mem_row_major);
    __syncthreads();

    const int orow = tid >> 1;
    const int ocol = (tid & 1) * 32;
    float* crow = &C[(size_t)(m0 + orow) * N_total + n0 + ocol];
    const float* srow = &Cst[orow * 72 + ocol];
#pragma unroll
    for (int c = 0; c < 32; c += 4) {
        float4 o;
        o.x = srow[c]     + __ldg(&bias[n0 + ocol + c]);
        o.y = srow[c + 1] + __ldg(&bias[n0 + ocol + c + 1]);
        o.z = srow[c + 2] + __ldg(&bias[n0 + ocol + c + 2]);
        o.w = srow[c + 3] + __ldg(&bias[n0 + ocol + c + 3]);
        *(float4*)&crow[c] = o;
    }
}

// ---------------------------------------------------------------------------
// fp32 GEMM (R11 verbatim) — FC head.
// ---------------------------------------------------------------------------
__global__ void __launch_bounds__(256) gemm_nt(
    const float* __restrict__ A, const float* __restrict__ Bm,
    const float* __restrict__ bias, float* __restrict__ C,
    int M, int N, int K)
{
    const int BM = 128, BN = 64, BK = 16;
    __shared__ float As[2][BK * BM];
    __shared__ float Bs[2][BK * BN];

    int tid = threadIdx.x;
    int tx = tid & 15;
    int ty = tid >> 4;
    int m0 = blockIdx.y * BM;
    int n0 = blockIdx.x * BN;

    const int a_row0 = tid >> 2, a_c4 = tid & 3;
    const int b_row  = tid >> 2, b_c4 = tid & 3;

    uint64_t acc2[4][4];
#pragma unroll
    for (int i = 0; i < 4; i++)
#pragma unroll
        for (int j = 0; j < 4; j++) acc2[i][j] = 0ull;

    float4 a_stg0, a_stg1, b_stg;

    a_stg0 = *(const float4*)&A[(size_t)(m0 + a_row0) * K + a_c4 * 4];
    a_stg1 = *(const float4*)&A[(size_t)(m0 + a_row0 + 64) * K + a_c4 * 4];
    b_stg  = *(const float4*)&Bm[(size_t)(n0 + b_row) * K + b_c4 * 4];
    {
        float* as = As[0]; float* bs = Bs[0];
        as[(a_c4 * 4 + 0) * BM + a_row0] = a_stg0.x;
        as[(a_c4 * 4 + 1) * BM + a_row0] = a_stg0.y;
        as[(a_c4 * 4 + 2) * BM + a_row0] = a_stg0.z;
        as[(a_c4 * 4 + 3) * BM + a_row0] = a_stg0.w;
        as[(a_c4 * 4 + 0) * BM + a_row0 + 64] = a_stg1.x;
        as[(a_c4 * 4 + 1) * BM + a_row0 + 64] = a_stg1.y;
        as[(a_c4 * 4 + 2) * BM + a_row0 + 64] = a_stg1.z;
        as[(a_c4 * 4 + 3) * BM + a_row0 + 64] = a_stg1.w;
        bs[(b_c4 * 4 + 0) * BN + b_row] = b_stg.x;
        bs[(b_c4 * 4 + 1) * BN + b_row] = b_stg.y;
        bs[(b_c4 * 4 + 2) * BN + b_row] = b_stg.z;
        bs[(b_c4 * 4 + 3) * BN + b_row] = b_stg.w;
    }
    __syncthreads();

    int p = 0;
    for (int kt = 0; kt < K; kt += BK) {
        const bool has_next = (kt + BK) < K;
        if (has_next) {
            a_stg0 = *(const float4*)&A[(size_t)(m0 + a_row0) * K + kt + BK + a_c4 * 4];
            a_stg1 = *(const float4*)&A[(size_t)(m0 + a_row0 + 64) * K + kt + BK + a_c4 * 4];
            b_stg  = *(const float4*)&Bm[(size_t)(n0 + b_row) * K + kt + BK + b_c4 * 4];
        }

        const float* as = As[p];
        const float* bs = Bs[p];
#pragma unroll
        for (int k = 0; k < BK; k++) {
            const uint64_t* a2 = (const uint64_t*)&as[k * BM + ty * 8];
            uint64_t av0 = a2[0], av1 = a2[1], av2 = a2[2], av3 = a2[3];
            float4 bq = *(const float4*)&bs[k * BN + tx * 4];
            uint64_t b0 = dup2_(bq.x), b1 = dup2_(bq.y);
            uint64_t b2 = dup2_(bq.z), b3 = dup2_(bq.w);
            fma2_(acc2[0][0], av0, b0); fma2_(acc2[0][1], av0, b1);
            fma2_(acc2[0][2], av0, b2); fma2_(acc2[0][3], av0, b3);
            fma2_(acc2[1][0], av1, b0); fma2_(acc2[1][1], av1, b1);
            fma2_(acc2[1][2], av1, b2); fma2_(acc2[1][3], av1, b3);
            fma2_(acc2[2][0], av2, b0); fma2_(acc2[2][1], av2, b1);
            fma2_(acc2[2][2], av2, b2); fma2_(acc2[2][3], av2, b3);
            fma2_(acc2[3][0], av3, b0); fma2_(acc2[3][1], av3, b1);
            fma2_(acc2[3][2], av3, b2); fma2_(acc2[3][3], av3, b3);
        }

        if (has_next) {
            float* asn = As[p ^ 1]; float* bsn = Bs[p ^ 1];
            asn[(a_c4 * 4 + 0) * BM + a_row0] = a_stg0.x;
            asn[(a_c4 * 4 + 1) * BM + a_row0] = a_stg0.y;
            asn[(a_c4 * 4 + 2) * BM + a_row0] = a_stg0.z;
            asn[(a_c4 * 4 + 3) * BM + a_row0] = a_stg0.w;
            asn[(a_c4 * 4 + 0) * BM + a_row0 + 64] = a_stg1.x;
            asn[(a_c4 * 4 + 1) * BM + a_row0 + 64] = a_stg1.y;
            asn[(a_c4 * 4 + 2) * BM + a_row0 + 64] = a_stg1.z;
            asn[(a_c4 * 4 + 3) * BM + a_row0 + 64] = a_stg1.w;
            bsn[(b_c4 * 4 + 0) * BN + b_row] = b_stg.x;
            bsn[(b_c4 * 4 + 1) * BN + b_row] = b_stg.y;
            bsn[(b_c4 * 4 + 2) * BN + b_row] = b_stg.z;
            bsn[(b_c4 * 4 + 3) * BN + b_row] = b_stg.w;
            __syncthreads();
        }
        p ^= 1;
    }

    float4 bv = *(const float4*)&bias[n0 + tx * 4];
#pragma unroll
    for (int ii = 0; ii < 4; ii++) {
        float4 oe, oo;
        oe.x = f2lo_(acc2[ii][0]) + bv.x;
        oe.y = f2lo_(acc2[ii][1]) + bv.y;
        oe.z = f2lo_(acc2[ii][2]) + bv.z;
        oe.w = f2lo_(acc2[ii][3]) + bv.w;
        oo.x = f2hi_(acc2[ii][0]) + bv.x;
        oo.y = f2hi_(acc2[ii][1]) + bv.y;
        oo.z = f2hi_(acc2[ii][2]) + bv.z;
        oo.w = f2hi_(acc2[ii][3]) + bv.w;
        *(float4*)&C[(size_t)(m0 + ty * 8 + 2 * ii) * N + n0 + tx * 4] = oe;
        *(float4*)&C[(size_t)(m0 + ty * 8 + 2 * ii + 1) * N + n0 + tx * 4] = oo;
    }
}

// ---------------------------------------------------------------------------
// GRU recurrent scan — R13/R15 version; optional bf16 hi/lo emission of h.
// ---------------------------------------------------------------------------
#define HQ_HALF 260
#define HQ_P    (2 * HQ_HALF)
#define TXB     2048u

__global__ void __cluster_dims__(4, 1, 1) __launch_bounds__(384, 1)
gru_scan(const float* __restrict__ gates, const float* __restrict__ Whh,
         const float* __restrict__ bhh, float* __restrict__ hout,
         __nv_bfloat16* __restrict__ houth, __nv_bfloat16* __restrict__ houtl,
         int wsplit)
{
    __shared__ __align__(16) float hq[2 * HQ_P];
    __shared__ __align__(16) float stag[2][128];
    __shared__ float gh_s[2 * 192];
    __shared__ float bh_s[192];
    __shared__ __align__(8) uint64_t mbar_s[2];

    int tid = threadIdx.x;
    uint32_t rank;
    asm("mov.u32 %0, %%cluster_ctarank;" : "=r"(rank));
    int b0 = (blockIdx.x >> 2) * 2;

    const int row = tid >> 1;
    const int ks  = tid & 1;
    const int g   = row >> 6;
    const int jl  = row & 63;
    const int grow = g * H_ + (int)rank * 64 + jl;

    uint64_t wr[64];
    const uint64_t* wsrc = (const uint64_t*)&Whh[(size_t)grow * H_ + ks * 128];
#pragma unroll
    for (int kk = 0; kk < 64; kk++) wr[kk] = wsrc[kk];

    uint32_t hq_u32   = (uint32_t)__cvta_generic_to_shared(hq);
    uint32_t stag_u32 = (uint32_t)__cvta_generic_to_shared(stag);
    uint32_t mbar_u32 = (uint32_t)__cvta_generic_to_shared(mbar_s);

    if (tid < 192) {
        int gg = tid >> 6, jj = tid & 63;
        bh_s[tid] = bhh[gg * H_ + (int)rank * 64 + jj];
    }
    for (int i = tid; i < 2 * HQ_P; i += 384) hq[i] = 0.0f;
    if (tid == 0) {
        mbar_init_(mbar_u32, 1);
        mbar_init_(mbar_u32 + 8, 1);
        mbar_arm_(mbar_u32 + 8, TXB);
    }
    __syncthreads();
    asm volatile("barrier.cluster.arrive.aligned;" ::: "memory");
    asm volatile("barrier.cluster.wait.aligned;" ::: "memory");

    const uint32_t ks_off = (uint32_t)ks * (HQ_HALF * 4);

    const int jl_e = tid & 63;
    const int bb   = (tid >> 6) & 1;
    const int jg   = (int)rank * 64 + jl_e;
    const int sidx = ((jl_e >> 1) << 2) + bb * 2 + (jl_e & 1);
    const uint32_t dst_off = (rank >> 1) * (HQ_HALF * 4) + (rank & 1) * 512;

    float hprev = 0.0f;
    uint32_t ph = 0;
    for (int t = 0; t < T_; t++) {
        const int buf = t & 1;
        const int nxt = buf ^ 1;

        float xr = 0.f, xz = 0.f, xn = 0.f;
        if (tid < 128) {
            const float* gp = &gates[((size_t)(b0 + bb) * T_ + t) * G3];
            xr = __ldg(gp + jg);
            xz = __ldg(gp + 256 + jg);
            xn = __ldg(gp + 512 + jg);
        }

        if (t) {
            mbar_wait_(mbar_u32 + buf * 8, (ph >> buf) & 1u);
            ph ^= (1u << buf);
        }
        if (tid == 0) mbar_arm_(mbar_u32 + buf * 8, TXB);

        uint32_t hb = hq_u32 + (uint32_t)buf * (HQ_P * 4) + ks_off;
        uint64_t a00 = 0, a01 = 0, a10 = 0, a11 = 0;
#pragma unroll
        for (int kk = 0; kk < 64; kk += 2) {
            uint64_t hx0, hy0, hx1, hy1;
            asm volatile("ld.shared.v2.u64 {%0,%1}, [%2];"
                         : "=l"(hx0), "=l"(hy0) : "r"(hb + kk * 16));
            asm volatile("ld.shared.v2.u64 {%0,%1}, [%2];"
                         : "=l"(hx1), "=l"(hy1) : "r"(hb + kk * 16 + 16));
            fma2_(a00, wr[kk], hx0);
            fma2_(a10, wr[kk], hy0);
            fma2_(a01, wr[kk + 1], hx1);
            fma2_(a11, wr[kk + 1], hy1);
        }
        float s0 = (f2lo_(a00) + f2hi_(a00)) + (f2lo_(a01) + f2hi_(a01));
        float s1 = (f2lo_(a10) + f2hi_(a10)) + (f2lo_(a11) + f2hi_(a11));
        s0 += __shfl_xor_sync(0xffffffffu, s0, 1);
        s1 += __shfl_xor_sync(0xffffffffu, s1, 1);
        if (ks == 0) {
            float bh = bh_s[row];
            gh_s[row]       = s0 + bh;
            gh_s[192 + row] = s1 + bh;
        }
        __syncthreads();

        if (tid < 128) {
            float r = sigmoid_hw_(xr + gh_s[bb * 192 + jl_e]);
            float z = sigmoid_hw_(xz + gh_s[bb * 192 + 64 + jl_e]);
            float n = tanh_hw_(xn + r * gh_s[bb * 192 + 128 + jl_e]);
            float hnew = (1.0f - z) * n + z * hprev;
            hprev = hnew;

            stag[nxt][sidx] = hnew;
            size_t oidx = ((size_t)(b0 + bb) * T_ + t) * H_ + jg;
            hout[oidx] = hnew;
            if (wsplit) {
                __nv_bfloat16 hhi = __float2bfloat16(hnew);
                houth[oidx] = hhi;
                houtl[oidx] = __float2bfloat16(hnew - __bfloat162float(hhi));
            }

            asm volatile("bar.sync 1, 128;" ::: "memory");
            if (tid < 4) {
                asm volatile("fence.proxy.async.shared::cta;" ::: "memory");
                uint32_t src = stag_u32 + (uint32_t)nxt * 512;
                uint32_t dst = hq_u32 + (uint32_t)nxt * (HQ_P * 4) + dst_off;
                uint32_t mb  = mbar_u32 + nxt * 8;
                asm volatile(
                    "{\n\t.reg .b32 ra, rb;\n\t"
                    "mapa.shared::cluster.u32 ra, %0, %3;\n\t"
                    "mapa.shared::cluster.u32 rb, %1, %3;\n\t"
                    "cp.async.bulk.shared::cluster.shared::cta."
                    "mbarrier::complete_tx::bytes [ra], [%2], 512, [rb];\n\t}"
                    :: "r"(dst), "r"(mb), "r"(src), "r"((uint32_t)tid) : "memory");
            }
        }
    }

    mbar_wait_(mbar_u32, ph & 1u);
    asm volatile("barrier.cluster.arrive.aligned;" ::: "memory");
    asm volatile("barrier.cluster.wait.aligned;" ::: "memory");
}

// ---------------------------------------------------------------------------
extern "C" void kernel_launch(void* const* d_in, const int* in_sizes, int n_in,
                              void* d_out, int out_size)
{
    const float* x    = (const float*)d_in[0];
    const float* Wih0 = (const float*)d_in[1];
    const float* Whh0 = (const float*)d_in[2];
    const float* bih0 = (const float*)d_in[3];
    const float* bhh0 = (const float*)d_in[4];
    const float* Wih1 = (const float*)d_in[5];
    const float* Whh1 = (const float*)d_in[6];
    const float* bih1 = (const float*)d_in[7];
    const float* bhh1 = (const float*)d_in[8];
    const float* fcw  = (const float*)d_in[9];
    const float* fcb  = (const float*)d_in[10];
    float* out = (float*)d_out;

    float *gates, *h;
    __nv_bfloat16 *xh, *xl, *hh, *hl, *wh, *wl;
    cudaGetSymbolAddress((void**)&gates, g_gates);
    cudaGetSymbolAddress((void**)&h, g_h);
    cudaGetSymbolAddress((void**)&xh, g_xh);
    cudaGetSymbolAddress((void**)&xl, g_xl);
    cudaGetSymbolAddress((void**)&hh, g_hh);
    cudaGetSymbolAddress((void**)&hl, g_hl);
    cudaGetSymbolAddress((void**)&wh, g_wh);
    cudaGetSymbolAddress((void**)&wl, g_wl);

    const int M = B_ * T_;

    // Pre-split x and W_ih0 to bf16 hi/lo
    int n4x = (B_ * T_ * I_) / 4;
    cvt_split<<<(n4x + 255) / 256, 256>>>(x, xh, xl, n4x);
    int n4w0 = (G3 * I_) / 4;
    cvt_split<<<(n4w0 + 255) / 256, 256>>>(Wih0, wh, wl, n4w0);

    // Layer 0
    gemm_wmma2<<<dim3(G3 / 64, M / 128), 256, GW2_SMEM>>>(
        xh, xl, wh, wl, bih0, gates, G3, I_);
    gru_scan<<<128, 384>>>(gates, Whh0, bhh0, h, hh, hl, 1);

    // Layer 1 (W_ih1 split after gemm0 has consumed wh/wl)
    int n4w1 = (G3 * H_) / 4;
    cvt_split<<<(n4w1 + 255) / 256, 256>>>(Wih1, wh, wl, n4w1);
    gemm_wmma2<<<dim3(G3 / 64, M / 128), 256, GW2_SMEM>>>(
        hh, hl, wh, wl, bih1, gates, G3, H_);
    gru_scan<<<128, 384>>>(gates, Whh1, bhh1, h, hh, hl, 0);

    // Classifier head (fp32)
    gemm_nt<<<dim3(C_ / 64, M / 128), dim3(256)>>>(h, fcw, fcb, out, M, C_, H_);
}